// round 2
// baseline (speedup 1.0000x reference)
#include <cuda_runtime.h>
#include <cstdint>

#define HIDDEN 256
#define H4     64
#define MAXD   512      // degree table capacity; P(deg >= 512) ~ 0 for Binomial(3.2M, 1e-5)
#define NMAX   131072   // >= num_nodes

// ---------------- static device scratch (no allocations allowed) ----------------
__device__ int   g_deg[NMAX];
__device__ float g_C[HIDDEN];
__device__ float g_V[4][HIDDEN];                       // V0=deg, V1=bet, V2=clo, V3=eig
__device__ __align__(16) float g_G[MAXD][HIDDEN];      // h_pre at t=0 per degree
__device__ __align__(16) float g_T0[MAXD][HIDDEN];     // out = T0 + t*T1 (fast path)
__device__ __align__(16) float g_T1[MAXD][HIDDEN];
__device__ int   g_flag[MAXD];           // 1 => ambiguous relu sign for this degree
__device__ int   g_tmaxbits;             // max over nodes of deg*|noise| (float bits)
__device__ int   g_is32;                 // 1 => edge_index stored as int32

// ---------------- kernels ----------------

// Detect edge_index element width. If int64 (values < 2^31), every odd 32-bit
// word in the first n_edges entries is the zero high-half. If int32, odd words
// are random node ids (~all nonzero). Deterministic for fixed input.
__global__ void k_detect(const int* __restrict__ w, int nwords) {
    __shared__ int any_nonzero;
    if (threadIdx.x == 0) any_nonzero = 0;
    __syncthreads();
    int nz = 0;
    for (int i = threadIdx.x; i < nwords / 2; i += blockDim.x)
        if (w[2 * i + 1] != 0) nz = 1;
    if (nz) any_nonzero = 1;
    __syncthreads();
    if (threadIdx.x == 0) g_is32 = any_nonzero;
}

__global__ void k_zero(int num_nodes) {
    int i = blockIdx.x * blockDim.x + threadIdx.x;
    if (i < num_nodes) g_deg[i] = 0;
    if (i < MAXD)      g_flag[i] = 0;
    if (i == 0)        g_tmaxbits = 0;
}

__global__ void k_degree(const void* __restrict__ ei, int n_edges, int num_nodes) {
    int i = blockIdx.x * blockDim.x + threadIdx.x;
    int stride = gridDim.x * blockDim.x;
    if (g_is32) {
        const int* col = ((const int*)ei) + n_edges;          // edge_index[1], int32
        for (; i < n_edges; i += stride) {
            int idx = col[i];
            if ((unsigned)idx < (unsigned)num_nodes) atomicAdd(&g_deg[idx], 1);
        }
    } else {
        const long long* col = ((const long long*)ei) + n_edges;  // int64
        for (; i < n_edges; i += stride) {
            long long v = col[i];
            if ((unsigned long long)v < (unsigned long long)num_nodes)
                atomicAdd(&g_deg[(int)v], 1);
        }
    }
}

__global__ void k_stats(const float* __restrict__ noise, int num_nodes) {
    int i = blockIdx.x * blockDim.x + threadIdx.x;
    float m = 0.0f;
    if (i < num_nodes) m = (float)g_deg[i] * fabsf(noise[i]);
    #pragma unroll
    for (int s = 16; s > 0; s >>= 1)
        m = fmaxf(m, __shfl_xor_sync(0xFFFFFFFFu, m, s));
    if ((threadIdx.x & 31) == 0 && m > 0.0f)
        atomicMax(&g_tmaxbits, __float_as_int(m));   // nonneg floats: int cmp ok
}

__global__ void k_vc(const float* __restrict__ Wd, const float* __restrict__ bd,
                     const float* __restrict__ Wb, const float* __restrict__ bb,
                     const float* __restrict__ Wc, const float* __restrict__ bc,
                     const float* __restrict__ We, const float* __restrict__ be,
                     const float* __restrict__ W1, const float* __restrict__ b1) {
    int o = threadIdx.x;                 // one thread per hidden unit
    float c = b1[o], v0 = 0.f, v1 = 0.f, v2 = 0.f, v3 = 0.f;
    for (int i = 0; i < H4; i++) {
        float w;
        w = W1[(i      ) * HIDDEN + o];  v0 = fmaf(Wd[i], w, v0);  c = fmaf(bd[i], w, c);
        w = W1[(H4  + i) * HIDDEN + o];  v1 = fmaf(Wb[i], w, v1);  c = fmaf(bb[i], w, c);
        w = W1[(128 + i) * HIDDEN + o];  v2 = fmaf(Wc[i], w, v2);  c = fmaf(bc[i], w, c);
        w = W1[(192 + i) * HIDDEN + o];  v3 = fmaf(We[i], w, v3);  c = fmaf(be[i], w, c);
    }
    g_C[o] = c; g_V[0][o] = v0; g_V[1][o] = v1; g_V[2][o] = v2; g_V[3][o] = v3;
}

__global__ void k_table(const float* __restrict__ W2, const float* __restrict__ b2,
                        float inv_nm1) {
    __shared__ float Gs[HIDDEN], V1s[HIDDEN];
    __shared__ unsigned char cls[HIDDEN];
    int d = blockIdx.x, j = threadIdx.x;

    float tmax = __int_as_float(g_tmaxbits) * 0.1f * inv_nm1;  // max |t| over all nodes
    float dc  = (float)d * inv_nm1;
    float clo = 1.0f / (dc + 1e-8f);
    float eig = sqrtf(dc);

    float v1 = g_V[1][j];
    float g  = g_C[j] + dc * (g_V[0][j] + v1) + clo * g_V[2][j] + eig * g_V[3][j];
    Gs[j] = g; V1s[j] = v1; g_G[d][j] = g;

    // conservative classification margin (covers fp32 reassociation differences)
    float w  = tmax * fabsf(v1) + 1e-4f + 1e-6f * fabsf(g);
    unsigned char cl = (g - w > 0.0f) ? 1 : ((g + w < 0.0f) ? 0 : 2);
    cls[j] = cl;
    if (cl == 2) g_flag[d] = 1;          // benign race: all writers store 1
    __syncthreads();

    int o = j;
    float a0 = b2[o], a1 = 0.0f;
    for (int jj = 0; jj < HIDDEN; jj++) {
        if (cls[jj] == 1) {
            float w2 = W2[jj * HIDDEN + o];
            a0 = fmaf(Gs[jj],  w2, a0);
            a1 = fmaf(V1s[jj], w2, a1);
        }
    }
    g_T0[d][o] = a0;
    g_T1[d][o] = a1;
}

__global__ void k_main(const float* __restrict__ noise, float* __restrict__ out,
                       int num_nodes, float inv_nm1,
                       const float* __restrict__ W2, const float* __restrict__ b2) {
    int gwarp = (blockIdx.x * blockDim.x + threadIdx.x) >> 5;
    int lane  = threadIdx.x & 31;
    if (gwarp >= num_nodes) return;
    int n = gwarp;                                // one warp per node
    int d = g_deg[n];
    float t = 0.1f * ((float)d * inv_nm1) * noise[n];
    float* op = out + (size_t)n * HIDDEN;

    if (d < MAXD && g_flag[d] == 0) {
        // fast path: out = T0[d] + t*T1[d]   (table rows hot in L1/L2)
        const float4* t0 = (const float4*)g_T0[d];
        const float4* t1 = (const float4*)g_T1[d];
        float4* o4 = (float4*)op;
        #pragma unroll
        for (int v = 0; v < 2; v++) {
            int idx = v * 32 + lane;
            float4 a = t0[idx], b = t1[idx], r;
            r.x = fmaf(t, b.x, a.x);
            r.y = fmaf(t, b.y, a.y);
            r.z = fmaf(t, b.z, a.z);
            r.w = fmaf(t, b.w, a.w);
            o4[idx] = r;
        }
    } else {
        // exact slow path (statistically ~never taken): full relu + W2 row-walk
        float acc[8];
        #pragma unroll
        for (int k = 0; k < 8; k++) acc[k] = b2[lane + k * 32];
        float dc  = (float)d * inv_nm1;
        float clo = 1.0f / (dc + 1e-8f);
        float eig = sqrtf(dc);
        for (int j = 0; j < HIDDEN; j++) {
            float g = (d < MAXD) ? g_G[d][j]
                                 : g_C[j] + dc * (g_V[0][j] + g_V[1][j])
                                   + clo * g_V[2][j] + eig * g_V[3][j];
            float h = fmaxf(fmaf(t, g_V[1][j], g), 0.0f);
            const float* wrow = W2 + j * HIDDEN;
            #pragma unroll
            for (int k = 0; k < 8; k++)
                acc[k] = fmaf(h, wrow[lane + k * 32], acc[k]);
        }
        #pragma unroll
        for (int k = 0; k < 8; k++) op[lane + k * 32] = acc[k];
    }
}

// ---------------- launch ----------------
// metadata order: 0:x 1:edge_index 2:noise 3:W_deg 4:b_deg 5:W_bet 6:b_bet
//                 7:W_clo 8:b_clo 9:W_eig 10:b_eig 11:W1 12:b1 13:W2 14:b2
extern "C" void kernel_launch(void* const* d_in, const int* in_sizes, int n_in,
                              void* d_out, int out_size) {
    const void*  ei    = d_in[1];
    const float* noise = (const float*)d_in[2];
    const float *Wd = (const float*)d_in[3],  *bd = (const float*)d_in[4];
    const float *Wb = (const float*)d_in[5],  *bb = (const float*)d_in[6];
    const float *Wc = (const float*)d_in[7],  *bc = (const float*)d_in[8];
    const float *We = (const float*)d_in[9],  *be = (const float*)d_in[10];
    const float *W1 = (const float*)d_in[11], *b1 = (const float*)d_in[12];
    const float *W2 = (const float*)d_in[13], *b2 = (const float*)d_in[14];

    int num_nodes = in_sizes[0] / HIDDEN;
    int n_edges   = in_sizes[1] / 2;
    float inv_nm1 = 1.0f / (float)(num_nodes - 1);

    // dtype-width self-detection: inspect first 4096 32-bit words of row 0
    int nwords = 4096;
    if (nwords > n_edges) nwords = n_edges;   // stay within smallest possible buffer
    k_detect<<<1, 256>>>((const int*)ei, nwords);

    int tz = (num_nodes + 255) / 256;
    k_zero<<<tz, 256>>>(num_nodes);

    int db = (n_edges + 1023) / 1024;
    if (db > 4096) db = 4096;                 // grid-stride
    k_degree<<<db, 256>>>(ei, n_edges, num_nodes);

    k_stats<<<(num_nodes + 255) / 256, 256>>>(noise, num_nodes);

    k_vc<<<1, HIDDEN>>>(Wd, bd, Wb, bb, Wc, bc, We, be, W1, b1);

    k_table<<<MAXD, HIDDEN>>>(W2, b2, inv_nm1);

    int mb = (num_nodes + 7) / 8;             // 8 warps (nodes) per block
    k_main<<<mb, 256>>>(noise, (float*)d_out, num_nodes, inv_nm1, W2, b2);
}